// round 2
// baseline (speedup 1.0000x reference)
#include <cuda_runtime.h>
#include <cstdint>
#include <cstddef>

#define EMB_K   1024
#define DIMS    64
#define HW_     4096
#define NQ      65536
#define TPB     512
#define NBLK    (NQ / TPB)      // 128
#define CHUNK   128
#define QELEMS  (16 * 64 * 64 * 64)   // 1048576

__device__ float g_partial[NBLK];

__device__ __forceinline__ unsigned long long ffma2(unsigned long long a,
                                                    unsigned long long b,
                                                    unsigned long long c) {
    unsigned long long d;
    asm("fma.rn.f32x2 %0, %1, %2, %3;" : "=l"(d) : "l"(a), "l"(b), "l"(c));
    return d;
}

__device__ __forceinline__ unsigned long long pack2(float v) {
    unsigned long long r;
    asm("mov.b64 %0, {%1, %1};" : "=l"(r) : "f"(v));
    return r;
}

__device__ __forceinline__ void unpack2(unsigned long long p, float& lo, float& hi) {
    asm("mov.b64 {%0, %1}, %2;" : "=f"(lo), "=f"(hi) : "l"(p));
}

__global__ void __launch_bounds__(TPB, 1) vq_main(
    const float* __restrict__ in,     // [16,64,64,64] NCHW
    const float* __restrict__ emb,    // [1024,64]
    float* __restrict__ out_q,        // [16,64,64,64] NCHW
    float* __restrict__ out_idx)      // [65536] (indices as float)
{
    __shared__ float et[DIMS][CHUNK];   // d-major code tile: 32 KB
    __shared__ float enorm[EMB_K];      // 4 KB
    __shared__ float red[TPB];          // 2 KB

    const int t = threadIdx.x;
    const int n = blockIdx.x * TPB + t;       // query index
    const int b = n >> 12;                    // n / 4096
    const int hw = n & 4095;

    // ---- load query vector (coalesced across threads per channel) ----
    const float* xin = in + (size_t)b * (DIMS * HW_) + hw;
    float x[DIMS];
#pragma unroll
    for (int c = 0; c < DIMS; c++) x[c] = __ldg(xin + (size_t)c * HW_);

    // ---- precompute all code norms once (L2-hot embedding) ----
    for (int c = t; c < EMB_K; c += TPB) {
        const float4* er = (const float4*)(emb + (size_t)c * DIMS);
        float s = 0.f;
#pragma unroll
        for (int i = 0; i < 16; i++) {
            float4 v = __ldg(er + i);
            s += v.x * v.x + v.y * v.y + v.z * v.z + v.w * v.w;
        }
        enorm[c] = s;
    }
    __syncthreads();

    float best = 3.402823466e38f;
    int bidx = 0;

    for (int c0 = 0; c0 < EMB_K; c0 += CHUNK) {
        // ---- load chunk transposed into smem (conflict-free STS: lanes span codes) ----
#pragma unroll
        for (int i = 0; i < 4; i++) {
            int g = t + i * TPB;            // 0..2047
            int code = g & 127;
            int d = (g >> 7) * 4;           // 0,4,...,60
            float4 v = __ldg((const float4*)(emb + (size_t)(c0 + code) * DIMS + d));
            et[d + 0][code] = v.x;
            et[d + 1][code] = v.y;
            et[d + 2][code] = v.z;
            et[d + 3][code] = v.w;
        }
        __syncthreads();

        // ---- 16 codes per group, packed f32x2 accumulators ----
#pragma unroll 1
        for (int cg = 0; cg < CHUNK; cg += 16) {
            unsigned long long acc[8];
#pragma unroll
            for (int k = 0; k < 8; k++) acc[k] = 0ull;

#pragma unroll
            for (int d = 0; d < DIMS; d++) {
                unsigned long long xx = pack2(x[d]);
                const ulonglong2* row = (const ulonglong2*)&et[d][cg];  // 64B-aligned
                ulonglong2 p0 = row[0];
                ulonglong2 p1 = row[1];
                ulonglong2 p2 = row[2];
                ulonglong2 p3 = row[3];
                acc[0] = ffma2(xx, p0.x, acc[0]);
                acc[1] = ffma2(xx, p0.y, acc[1]);
                acc[2] = ffma2(xx, p1.x, acc[2]);
                acc[3] = ffma2(xx, p1.y, acc[3]);
                acc[4] = ffma2(xx, p2.x, acc[4]);
                acc[5] = ffma2(xx, p2.y, acc[5]);
                acc[6] = ffma2(xx, p3.x, acc[6]);
                acc[7] = ffma2(xx, p3.y, acc[7]);
            }

#pragma unroll
            for (int k = 0; k < 8; k++) {
                float lo, hi;
                unpack2(acc[k], lo, hi);
                int c = c0 + cg + 2 * k;
                float v0 = fmaf(-2.f, lo, enorm[c]);
                float v1 = fmaf(-2.f, hi, enorm[c + 1]);
                // ascending-order strict < keeps first index on ties (jnp.argmin)
                if (v0 < best) { best = v0; bidx = c; }
                if (v1 < best) { best = v1; bidx = c + 1; }
            }
        }
        __syncthreads();
    }

    // ---- fused epilogue: index, gather, quantized NCHW write, exact loss ----
    out_idx[n] = (float)bidx;

    const float4* er = (const float4*)(emb + (size_t)bidx * DIMS);
    float* oq = out_q + (size_t)b * (DIMS * HW_) + hw;
    float loss = 0.f;
#pragma unroll
    for (int i = 0; i < 16; i++) {
        float4 v = __ldg(er + i);
        int c = i * 4;
        float d0 = v.x - x[c + 0];
        float d1 = v.y - x[c + 1];
        float d2 = v.z - x[c + 2];
        float d3 = v.w - x[c + 3];
        loss += d0 * d0 + d1 * d1 + d2 * d2 + d3 * d3;
        oq[(size_t)(c + 0) * HW_] = v.x;
        oq[(size_t)(c + 1) * HW_] = v.y;
        oq[(size_t)(c + 2) * HW_] = v.z;
        oq[(size_t)(c + 3) * HW_] = v.w;
    }

    // deterministic block reduction
    red[t] = loss;
    __syncthreads();
    for (int s = TPB / 2; s > 0; s >>= 1) {
        if (t < s) red[t] += red[t + s];
        __syncthreads();
    }
    if (t == 0) g_partial[blockIdx.x] = red[0];
}

__global__ void vq_finalize(float* __restrict__ out0) {
    if (threadIdx.x == 0) {
        float s = 0.f;
        for (int i = 0; i < NBLK; i++) s += g_partial[i];
        out0[0] = 0.25f * s * (1.0f / (float)QELEMS);
    }
}

extern "C" void kernel_launch(void* const* d_in, const int* in_sizes, int n_in,
                              void* d_out, int out_size) {
    const float* in  = (const float*)d_in[0];
    const float* emb = (const float*)d_in[1];
    // defensive: identify by element count (inputs=1048576, embedding=65536)
    if (n_in >= 2 && in_sizes[0] == EMB_K * DIMS && in_sizes[1] == QELEMS) {
        const float* tmp = in; in = emb; emb = tmp;
    }

    float* out = (float*)d_out;
    float* out_q   = out + 1;               // quantized, NCHW
    float* out_idx = out + 1 + QELEMS;      // encoding indices (as float)

    vq_main<<<NBLK, TPB>>>(in, emb, out_q, out_idx);
    vq_finalize<<<1, 32>>>(out);
}

// round 7
// speedup vs baseline: 1.6622x; 1.6622x over previous
#include <cuda_runtime.h>
#include <cuda_bf16.h>
#include <cstdint>
#include <cstddef>

#define EMB_K   1024
#define DIMS    64
#define HW_     4096
#define QELEMS  (16*64*64*64)
#define NCTA    512
#define TPB     256
#define MARGIN  0.75f
#define CAP     8
#define RSTRIDE 144          // smem row stride (bytes): 16B-aligned, bank-staggered

// dynamic smem layout
#define OFF_A    0                      // 128 x 144B  = 18432
#define OFF_B    18432                  // 256 x 144B  = 36864 (reused as cand-idx lists)
#define OFF_EN   55296                  // 1024 f32    = 4096
#define OFF_CST  59392                  // 256 thr x 2 rows x CAP float2 = 32768
#define OFF_CNT  92160                  // 128 int
#define OFF_RB   92672                  // 128 f32
#define OFF_RED  93184                  // 128 f32
#define SMEM_TOTAL 93696

__device__ __nv_bfloat16 g_embh[EMB_K * DIMS];
__device__ float g_enorm[EMB_K];
__device__ float g_partial[NCTA];

__device__ __forceinline__ uint32_t smem_u32(const void* p) {
    uint32_t a;
    asm("{ .reg .u64 t; cvta.to.shared.u64 t, %1; cvt.u32.u64 %0, t; }" : "=r"(a) : "l"(p));
    return a;
}

__device__ __forceinline__ void ldsm4(uint32_t* r, uint32_t addr) {
    asm volatile("ldmatrix.sync.aligned.m8n8.x4.shared.b16 {%0,%1,%2,%3}, [%4];"
                 : "=r"(r[0]), "=r"(r[1]), "=r"(r[2]), "=r"(r[3]) : "r"(addr));
}

__device__ __forceinline__ void mma16816(float* c, const uint32_t* a, const uint32_t* b) {
    asm volatile("mma.sync.aligned.m16n8k16.row.col.f32.bf16.bf16.f32 "
                 "{%0,%1,%2,%3}, {%4,%5,%6,%7}, {%8,%9}, {%0,%1,%2,%3};"
                 : "+f"(c[0]), "+f"(c[1]), "+f"(c[2]), "+f"(c[3])
                 : "r"(a[0]), "r"(a[1]), "r"(a[2]), "r"(a[3]), "r"(b[0]), "r"(b[1]));
}

// margin-candidate tracker (stack lives in smem; rare path)
__device__ __forceinline__ void upd(float& best, int& nc, float2* st, float d, int ci) {
    if (d < best + MARGIN) {
        if (d < best) best = d;
        if (nc == CAP) {                       // compact against improved best
            int m = 0;
#pragma unroll
            for (int q = 0; q < CAP; q++) {
                float2 e = st[q];
                if (e.x < best + MARGIN) st[m++] = e;
            }
            nc = m;
        }
        if (nc < CAP) {
            st[nc] = make_float2(d, __int_as_float(ci));
            nc++;
        } else {                               // replace worst
            int wq = 0; float wd = st[0].x;
#pragma unroll
            for (int q = 1; q < CAP; q++) { float v = st[q].x; if (v > wd) { wd = v; wq = q; } }
            if (d < wd) st[wq] = make_float2(d, __int_as_float(ci));
        }
    }
}

// ---------------- precompute: bf16 table + exact fp32 norms ----------------
__global__ void vq_pre(const float* __restrict__ emb) {
    int c = blockIdx.x * blockDim.x + threadIdx.x;
    if (c >= EMB_K) return;
    const float4* er = (const float4*)(emb + (size_t)c * DIMS);
    float s = 0.f;
#pragma unroll
    for (int i = 0; i < 16; i++) {
        float4 v = __ldg(er + i);
        s += v.x * v.x + v.y * v.y + v.z * v.z + v.w * v.w;
        __nv_bfloat162 h0 = __floats2bfloat162_rn(v.x, v.y);
        __nv_bfloat162 h1 = __floats2bfloat162_rn(v.z, v.w);
        ((__nv_bfloat162*)g_embh)[c * 32 + 2 * i]     = h0;
        ((__nv_bfloat162*)g_embh)[c * 32 + 2 * i + 1] = h1;
    }
    g_enorm[c] = s;
}

// ---------------- main kernel ----------------
__global__ void __launch_bounds__(TPB, 2) vq_tc(
    const float* __restrict__ in,     // [16,64,64,64] NCHW
    const float* __restrict__ emb,    // [1024,64] fp32 (exact re-rank)
    float* __restrict__ out_q,
    float* __restrict__ out_idx)
{
    extern __shared__ char smem[];
    const uint32_t sb = smem_u32(smem);
    const int t = threadIdx.x;
    const int lane = t & 31;
    const int w = t >> 5;
    const int n0blk = blockIdx.x * 128;
    const int b = n0blk >> 12;
    const int hw0 = n0blk & 4095;

    float* en = (float*)(smem + OFF_EN);
#pragma unroll
    for (int i = 0; i < 4; i++) en[t + i * TPB] = g_enorm[t + i * TPB];
    if (t < 128) ((int*)(smem + OFF_CNT))[t] = 0;

    // ---- A tile: 128 rows x 64 bf16, row stride 144B ----
    const int r = t & 127, h = t >> 7;          // h: which 32-channel half
    const float* inA = in + b * (DIMS * HW_) + hw0 + r;
#pragma unroll
    for (int j = 0; j < 16; j++) {
        int k = h * 32 + 2 * j;
        float f0 = __ldg(inA + (size_t)k * HW_);
        float f1 = __ldg(inA + (size_t)(k + 1) * HW_);
        __nv_bfloat162 hh = __floats2bfloat162_rn(f0, f1);
        *(uint32_t*)(smem + OFF_A + r * RSTRIDE + h * 64 + j * 4) = *(uint32_t*)&hh;
    }
    __syncthreads();

    // ---- A fragments: 16 regs, whole 16x64 warp tile ----
    const int wr0 = w * 16;
    uint32_t a[16];
#pragma unroll
    for (int j = 0; j < 4; j++) {
        uint32_t addr = sb + OFF_A + (uint32_t)((wr0 + (lane & 15)) * RSTRIDE)
                        + (uint32_t)(j * 32 + ((lane >> 4) * 16));
        ldsm4(a + 4 * j, addr);
    }

    const int g4 = lane >> 2, tid4 = lane & 3;
    float best0 = 3.4e38f, best1 = 3.4e38f;
    int nc0 = 0, nc1 = 0;
    float2* st0 = (float2*)(smem + OFF_CST) + (size_t)t * 2 * CAP;
    float2* st1 = st0 + CAP;

    for (int ch = 0; ch < 4; ch++) {
        if (ch) __syncthreads();                 // everyone done with prev B
        // ---- stage B chunk: 256 codes x 64 bf16 (coalesced LDG.128) ----
        const uint4* src = (const uint4*)g_embh + ch * 2048;
#pragma unroll
        for (int i = 0; i < 8; i++) {
            int idx = t + i * TPB;               // 0..2047
            uint4 v = __ldg(src + idx);
            *(uint4*)(smem + OFF_B + (idx >> 3) * RSTRIDE + (idx & 7) * 16) = v;
        }
        __syncthreads();

        const int cbase = ch * 256;
#pragma unroll 2
        for (int nt = 0; nt < 32; nt++) {
            uint32_t bb[8];
            uint32_t baddr = sb + OFF_B + (uint32_t)((nt * 8 + (lane & 7)) * RSTRIDE)
                             + (uint32_t)((lane >> 3) * 16);
            ldsm4(bb, baddr);          // ksteps 0,1
            ldsm4(bb + 4, baddr + 64); // ksteps 2,3
            float acc[4] = {0.f, 0.f, 0.f, 0.f};
            mma16816(acc, a + 0,  bb + 0);
            mma16816(acc, a + 4,  bb + 2);
            mma16816(acc, a + 8,  bb + 4);
            mma16816(acc, a + 12, bb + 6);

            int c0 = cbase + nt * 8 + 2 * tid4;
            float e0 = en[c0], e1 = en[c0 + 1];
            float d0 = fmaf(-2.f, acc[0], e0);   // row wr0+g4
            float d1 = fmaf(-2.f, acc[1], e1);
            float d2 = fmaf(-2.f, acc[2], e0);   // row wr0+8+g4
            float d3 = fmaf(-2.f, acc[3], e1);
            upd(best0, nc0, st0, d0, c0);
            upd(best0, nc0, st0, d1, c0 + 1);
            upd(best1, nc1, st1, d2, c0);
            upd(best1, nc1, st1, d3, c0 + 1);
        }
    }

    // ---- row-global coarse minima (quad shuffle: lanes g4*4 + 0..3) ----
#pragma unroll
    for (int o = 1; o <= 2; o <<= 1) {
        best0 = fminf(best0, __shfl_xor_sync(0xffffffffu, best0, o));
        best1 = fminf(best1, __shfl_xor_sync(0xffffffffu, best1, o));
    }
    float* rb = (float*)(smem + OFF_RB);
    if (tid4 == 0) { rb[wr0 + g4] = best0; rb[wr0 + 8 + g4] = best1; }
    __syncthreads();

    // ---- flush candidates within margin of the row-global best ----
    int* cnt = (int*)(smem + OFF_CNT);
    int* cix = (int*)(smem + OFF_B);             // B region reused: 128 rows x 32 idx
    {
        float th0 = rb[wr0 + g4] + MARGIN;
        float th1 = rb[wr0 + 8 + g4] + MARGIN;
        for (int q = 0; q < nc0; q++) {
            float2 e = st0[q];
            if (e.x < th0) {
                int p = atomicAdd(&cnt[wr0 + g4], 1);
                if (p < 32) cix[(wr0 + g4) * 32 + p] = __float_as_int(e.y);
            }
        }
        for (int q = 0; q < nc1; q++) {
            float2 e = st1[q];
            if (e.x < th1) {
                int p = atomicAdd(&cnt[wr0 + 8 + g4], 1);
                if (p < 32) cix[(wr0 + 8 + g4) * 32 + p] = __float_as_int(e.y);
            }
        }
    }
    __syncthreads();

    // ---- exact fp32 re-rank + outputs (threads 0..127, one query each) ----
    float* red = (float*)(smem + OFF_RED);
    if (t < 128) {
        const float* xin = in + b * (DIMS * HW_) + hw0 + t;
        float x[DIMS];
#pragma unroll
        for (int k = 0; k < DIMS; k++) x[k] = __ldg(xin + (size_t)k * HW_);

        int m = cnt[t]; if (m > 32) m = 32;
        float bd = 3.4e38f; int bi = 0x7fffffff;
        for (int q = 0; q < m; q++) {
            int ci = cix[t * 32 + q];
            const float4* er = (const float4*)(emb + (size_t)ci * DIMS);
            float dot = 0.f;
#pragma unroll
            for (int i = 0; i < 16; i++) {
                float4 v = __ldg(er + i);
                dot = fmaf(v.x, x[4 * i + 0], dot);
                dot = fmaf(v.y, x[4 * i + 1], dot);
                dot = fmaf(v.z, x[4 * i + 2], dot);
                dot = fmaf(v.w, x[4 * i + 3], dot);
            }
            float ed = fmaf(-2.f, dot, en[ci]);
            if (ed < bd || (ed == bd && ci < bi)) { bd = ed; bi = ci; }
        }

        int n = n0blk + t;
        out_idx[n] = (float)bi;
        float* oq = out_q + b * (DIMS * HW_) + hw0 + t;
        const float4* er = (const float4*)(emb + (size_t)bi * DIMS);
        float loss = 0.f;
#pragma unroll
        for (int i = 0; i < 16; i++) {
            float4 v = __ldg(er + i);
            int k = i * 4;
            float d0 = v.x - x[k + 0], d1 = v.y - x[k + 1];
            float d2 = v.z - x[k + 2], d3 = v.w - x[k + 3];
            loss += d0 * d0 + d1 * d1 + d2 * d2 + d3 * d3;
            oq[(size_t)(k + 0) * HW_] = v.x;
            oq[(size_t)(k + 1) * HW_] = v.y;
            oq[(size_t)(k + 2) * HW_] = v.z;
            oq[(size_t)(k + 3) * HW_] = v.w;
        }
        red[t] = loss;
    }
    __syncthreads();
#pragma unroll 1
    for (int s = 64; s > 0; s >>= 1) {
        if (t < s) red[t] += red[t + s];
        __syncthreads();
    }
    if (t == 0) g_partial[blockIdx.x] = red[0];
}

__global__ void vq_fin(float* __restrict__ out0) {
    __shared__ float sh[16];
    int t = threadIdx.x;                  // 512 threads
    float s = g_partial[t];
#pragma unroll
    for (int o = 16; o > 0; o >>= 1) s += __shfl_down_sync(0xffffffffu, s, o);
    if ((t & 31) == 0) sh[t >> 5] = s;
    __syncthreads();
    if (t < 16) {
        s = sh[t];
#pragma unroll
        for (int o = 8; o > 0; o >>= 1) s += __shfl_down_sync(0xffffu, s, o);
        if (t == 0) out0[0] = 0.25f * s * (1.0f / (float)QELEMS);
    }
}

extern "C" void kernel_launch(void* const* d_in, const int* in_sizes, int n_in,
                              void* d_out, int out_size) {
    const float* in  = (const float*)d_in[0];
    const float* emb = (const float*)d_in[1];
    if (n_in >= 2 && in_sizes[0] == EMB_K * DIMS && in_sizes[1] == QELEMS) {
        const float* tmp = in; in = emb; emb = tmp;
    }
    float* out = (float*)d_out;
    float* out_q   = out + 1;
    float* out_idx = out + 1 + QELEMS;

    static bool attr_done = false;
    if (!attr_done) {
        cudaFuncSetAttribute(vq_tc, cudaFuncAttributeMaxDynamicSharedMemorySize, SMEM_TOTAL);
        attr_done = true;
    }

    vq_pre<<<4, 256>>>(emb);
    vq_tc<<<NCTA, TPB, SMEM_TOTAL>>>(in, emb, out_q, out_idx);
    vq_fin<<<1, 512>>>(out);
}

// round 8
// speedup vs baseline: 2.0360x; 1.2248x over previous
#include <cuda_runtime.h>
#include <cuda_bf16.h>
#include <cstdint>
#include <cstddef>

#define EMB_K   1024
#define DIMS    64
#define HW_     4096
#define QELEMS  (16*64*64*64)
#define NCTA    512
#define TPB     256
#define MARGIN  3.0f
#define CAP     8
#define RS      80            // smem row stride (bytes) for 64B int8 rows

// smem layout
#define OFF_A    0                       // 128 x 80  = 10240
#define OFF_B    10240                   // 256 x 80  = 20480 (reused as cand-idx)
#define OFF_ENS  30720                   // 1024 float2 = 8192
#define OFF_SX   38912                   // 128 f32
#define OFF_CST  39424                   // 256 thr x 2 x CAP float2 = 32768
#define OFF_CNT  72192                   // 128 int
#define OFF_RB   72704                   // 128 f32
#define OFF_RED  73216                   // 128 f32
#define SMEM_TOTAL 73728                 // 72 KB -> 2 CTAs/SM

__device__ uint4 g_embq[EMB_K * 4];      // int8 codes, 64B/row
__device__ float g_enorm[EMB_K];
__device__ float g_escale[EMB_K];
__device__ float g_partial[NCTA];
__device__ unsigned int g_ticket;

__device__ __forceinline__ uint32_t smem_u32(const void* p) {
    uint32_t a;
    asm("{ .reg .u64 t; cvta.to.shared.u64 t, %1; cvt.u32.u64 %0, t; }" : "=r"(a) : "l"(p));
    return a;
}

__device__ __forceinline__ void ldsm4(uint32_t* r, uint32_t addr) {
    asm volatile("ldmatrix.sync.aligned.m8n8.x4.shared.b16 {%0,%1,%2,%3}, [%4];"
                 : "=r"(r[0]), "=r"(r[1]), "=r"(r[2]), "=r"(r[3]) : "r"(addr));
}

__device__ __forceinline__ void imma16832(int* c, const uint32_t* a, const uint32_t* b) {
    asm volatile("mma.sync.aligned.m16n8k32.row.col.s32.s8.s8.s32 "
                 "{%0,%1,%2,%3}, {%4,%5,%6,%7}, {%8,%9}, {%0,%1,%2,%3};"
                 : "+r"(c[0]), "+r"(c[1]), "+r"(c[2]), "+r"(c[3])
                 : "r"(a[0]), "r"(a[1]), "r"(a[2]), "r"(a[3]), "r"(b[0]), "r"(b[1]));
}

// margin-candidate tracker
__device__ __forceinline__ void upd(float& best, int& nc, float2* st, float d, int ci) {
    if (d < best + MARGIN) {
        if (d < best) best = d;
        if (nc == CAP) {
            int m = 0;
#pragma unroll
            for (int q = 0; q < CAP; q++) {
                float2 e = st[q];
                if (e.x < best + MARGIN) st[m++] = e;
            }
            nc = m;
        }
        if (nc < CAP) {
            st[nc] = make_float2(d, __int_as_float(ci));
            nc++;
        } else {
            int wq = 0; float wd = st[0].x;
#pragma unroll
            for (int q = 1; q < CAP; q++) { float v = st[q].x; if (v > wd) { wd = v; wq = q; } }
            if (d < wd) st[wq] = make_float2(d, __int_as_float(ci));
        }
    }
}

__device__ __forceinline__ int q8(float v, float inv) {
    int q = __float2int_rn(v * inv);
    return max(-127, min(127, q));
}

// ---------------- precompute: int8 table + scales + exact fp32 norms ----------------
__global__ void vq_pre(const float* __restrict__ emb) {
    int c = blockIdx.x * blockDim.x + threadIdx.x;
    if (c >= EMB_K) return;
    const float4* er = (const float4*)(emb + (size_t)c * DIMS);
    float4 v[16];
    float s = 0.f, am = 0.f;
#pragma unroll
    for (int i = 0; i < 16; i++) {
        v[i] = __ldg(er + i);
        s += v[i].x * v[i].x + v[i].y * v[i].y + v[i].z * v[i].z + v[i].w * v[i].w;
        am = fmaxf(am, fmaxf(fmaxf(fabsf(v[i].x), fabsf(v[i].y)),
                             fmaxf(fabsf(v[i].z), fabsf(v[i].w))));
    }
    float se  = am * (1.0f / 127.0f);
    float inv = (am > 0.f) ? (127.0f / am) : 0.f;
#pragma unroll
    for (int j = 0; j < 4; j++) {
        uint32_t w[4];
#pragma unroll
        for (int k = 0; k < 4; k++) {
            float4 t = v[j * 4 + k];
            int q0 = q8(t.x, inv), q1 = q8(t.y, inv), q2 = q8(t.z, inv), q3 = q8(t.w, inv);
            w[k] = (uint32_t)(q0 & 0xFF) | ((uint32_t)(q1 & 0xFF) << 8) |
                   ((uint32_t)(q2 & 0xFF) << 16) | ((uint32_t)(q3 & 0xFF) << 24);
        }
        g_embq[c * 4 + j] = make_uint4(w[0], w[1], w[2], w[3]);
    }
    g_enorm[c] = s;
    g_escale[c] = se;
}

// ---------------- fused main kernel ----------------
__global__ void __launch_bounds__(TPB, 2) vq_main(
    const float* __restrict__ in,
    const float* __restrict__ emb,
    float* __restrict__ out0,
    float* __restrict__ out_q,
    float* __restrict__ out_idx)
{
    extern __shared__ char smem[];
    const uint32_t sb = smem_u32(smem);
    const int t = threadIdx.x;
    const int lane = t & 31;
    const int w = t >> 5;
    const int n0blk = blockIdx.x * 128;
    const int b = n0blk >> 12;
    const int hw0 = n0blk & 4095;

    // ens[c] = (exact norm, int8 scale)
    float2* ens = (float2*)(smem + OFF_ENS);
#pragma unroll
    for (int i = 0; i < 4; i++) {
        int c = t + i * TPB;
        ens[c] = make_float2(g_enorm[c], g_escale[c]);
    }
    if (t < 128) ((int*)(smem + OFF_CNT))[t] = 0;

    // ---- A tile: query rows, int8-quantized, kept in regs for epilogue ----
    float x[DIMS];
    float* sx = (float*)(smem + OFF_SX);
    if (t < 128) {
        const float* xin = in + b * (DIMS * HW_) + hw0 + t;
        float am = 0.f;
#pragma unroll
        for (int k = 0; k < DIMS; k++) {
            x[k] = __ldg(xin + (size_t)k * HW_);
            am = fmaxf(am, fabsf(x[k]));
        }
        float sxv = am * (1.0f / 127.0f);
        float inv = (am > 0.f) ? (127.0f / am) : 0.f;
        sx[t] = sxv;
#pragma unroll
        for (int j = 0; j < 4; j++) {
            uint32_t wv[4];
#pragma unroll
            for (int k = 0; k < 4; k++) {
                int i0 = j * 16 + k * 4;
                int q0 = q8(x[i0 + 0], inv), q1 = q8(x[i0 + 1], inv);
                int q2 = q8(x[i0 + 2], inv), q3 = q8(x[i0 + 3], inv);
                wv[k] = (uint32_t)(q0 & 0xFF) | ((uint32_t)(q1 & 0xFF) << 8) |
                        ((uint32_t)(q2 & 0xFF) << 16) | ((uint32_t)(q3 & 0xFF) << 24);
            }
            *(uint4*)(smem + OFF_A + t * RS + j * 16) = make_uint4(wv[0], wv[1], wv[2], wv[3]);
        }
    }
    __syncthreads();

    // ---- A fragments: 8 regs cover 16 rows x 64 int8 ----
    const int wr0 = w * 16;
    uint32_t a[8];
    {
        uint32_t base = sb + OFF_A + (uint32_t)((wr0 + (lane & 15)) * RS) + (uint32_t)((lane >> 4) * 16);
        ldsm4(a, base);          // k 0..31
        ldsm4(a + 4, base + 32); // k 32..63
    }

    const int g4 = lane >> 2, tid4 = lane & 3;
    const float msx0 = -2.0f * sx[wr0 + g4];
    const float msx1 = -2.0f * sx[wr0 + 8 + g4];
    float best0 = 3.4e38f, best1 = 3.4e38f;
    int nc0 = 0, nc1 = 0;
    float2* st0 = (float2*)(smem + OFF_CST) + (size_t)t * 2 * CAP;
    float2* st1 = st0 + CAP;

    for (int ch = 0; ch < 4; ch++) {
        if (ch) __syncthreads();
        // stage B chunk: 256 codes x 64B int8
        const uint4* src = g_embq + ch * 1024;
#pragma unroll
        for (int i = 0; i < 4; i++) {
            int idx = t + i * TPB;                     // 0..1023
            uint4 v = __ldg(src + idx);
            *(uint4*)(smem + OFF_B + (idx >> 2) * RS + (idx & 3) * 16) = v;
        }
        __syncthreads();

        const int cbase = ch * 256;
#pragma unroll 2
        for (int nt = 0; nt < 32; nt++) {
            uint32_t bb[4];
            uint32_t baddr = sb + OFF_B + (uint32_t)((nt * 8 + (lane & 7)) * RS)
                             + (uint32_t)((lane >> 3) * 16);
            ldsm4(bb, baddr);
            int acc[4] = {0, 0, 0, 0};
            imma16832(acc, a, bb);           // k 0..31
            imma16832(acc, a + 4, bb + 2);   // k 32..63

            int c0 = cbase + nt * 8 + 2 * tid4;
            float4 es = *(const float4*)&ens[c0];      // en0, se0, en1, se1
            float s00 = msx0 * es.y, s01 = msx0 * es.w;
            float s10 = msx1 * es.y, s11 = msx1 * es.w;
            float d0 = fmaf((float)acc[0], s00, es.x);
            float d1 = fmaf((float)acc[1], s01, es.z);
            float d2 = fmaf((float)acc[2], s10, es.x);
            float d3 = fmaf((float)acc[3], s11, es.z);
            upd(best0, nc0, st0, d0, c0);
            upd(best0, nc0, st0, d1, c0 + 1);
            upd(best1, nc1, st1, d2, c0);
            upd(best1, nc1, st1, d3, c0 + 1);
        }
    }

    // ---- row-global coarse minima ----
#pragma unroll
    for (int o = 1; o <= 2; o <<= 1) {
        best0 = fminf(best0, __shfl_xor_sync(0xffffffffu, best0, o));
        best1 = fminf(best1, __shfl_xor_sync(0xffffffffu, best1, o));
    }
    float* rb = (float*)(smem + OFF_RB);
    if (tid4 == 0) { rb[wr0 + g4] = best0; rb[wr0 + 8 + g4] = best1; }
    __syncthreads();

    // ---- flush candidates within margin of the row-global best ----
    int* cnt = (int*)(smem + OFF_CNT);
    int* cix = (int*)(smem + OFF_B);
    {
        float th0 = rb[wr0 + g4] + MARGIN;
        float th1 = rb[wr0 + 8 + g4] + MARGIN;
        for (int q = 0; q < nc0; q++) {
            float2 e = st0[q];
            if (e.x < th0) {
                int p = atomicAdd(&cnt[wr0 + g4], 1);
                if (p < 32) cix[(wr0 + g4) * 32 + p] = __float_as_int(e.y);
            }
        }
        for (int q = 0; q < nc1; q++) {
            float2 e = st1[q];
            if (e.x < th1) {
                int p = atomicAdd(&cnt[wr0 + 8 + g4], 1);
                if (p < 32) cix[(wr0 + 8 + g4) * 32 + p] = __float_as_int(e.y);
            }
        }
    }
    __syncthreads();

    // ---- exact fp32 re-rank + outputs (x already in regs for t<128) ----
    float* red = (float*)(smem + OFF_RED);
    if (t < 128) {
        int m = cnt[t]; if (m > 32) m = 32;
        float bd = 3.4e38f; int bi = 0x7fffffff;
        for (int q = 0; q < m; q++) {
            int ci = cix[t * 32 + q];
            const float4* er = (const float4*)(emb + (size_t)ci * DIMS);
            float dot = 0.f;
#pragma unroll
            for (int i = 0; i < 16; i++) {
                float4 v = __ldg(er + i);
                dot = fmaf(v.x, x[4 * i + 0], dot);
                dot = fmaf(v.y, x[4 * i + 1], dot);
                dot = fmaf(v.z, x[4 * i + 2], dot);
                dot = fmaf(v.w, x[4 * i + 3], dot);
            }
            float ed = fmaf(-2.f, dot, ens[ci].x);
            if (ed < bd || (ed == bd && ci < bi)) { bd = ed; bi = ci; }
        }

        int n = n0blk + t;
        out_idx[n] = (float)bi;
        float* oq = out_q + b * (DIMS * HW_) + hw0 + t;
        const float4* er = (const float4*)(emb + (size_t)bi * DIMS);
        float loss = 0.f;
#pragma unroll
        for (int i = 0; i < 16; i++) {
            float4 v = __ldg(er + i);
            int k = i * 4;
            float d0 = v.x - x[k + 0], d1 = v.y - x[k + 1];
            float d2 = v.z - x[k + 2], d3 = v.w - x[k + 3];
            loss += d0 * d0 + d1 * d1 + d2 * d2 + d3 * d3;
            oq[(size_t)(k + 0) * HW_] = v.x;
            oq[(size_t)(k + 1) * HW_] = v.y;
            oq[(size_t)(k + 2) * HW_] = v.z;
            oq[(size_t)(k + 3) * HW_] = v.w;
        }
        red[t] = loss;
    }
    __syncthreads();
#pragma unroll 1
    for (int s = 64; s > 0; s >>= 1) {
        if (t < s) red[t] += red[t + s];
        __syncthreads();
    }

    // ---- fused finalize: last CTA reduces partials (deterministic order) ----
    __shared__ int slast;
    if (t == 0) {
        g_partial[blockIdx.x] = red[0];
        __threadfence();
        unsigned int old = atomicInc(&g_ticket, NCTA - 1);
        slast = (old == NCTA - 1);
    }
    __syncthreads();
    if (slast && t < 32) {
        __threadfence();
        float s = 0.f;
#pragma unroll
        for (int i = 0; i < NCTA / 32; i++) s += g_partial[t + 32 * i];
#pragma unroll
        for (int o = 16; o > 0; o >>= 1) s += __shfl_down_sync(0xffffffffu, s, o);
        if (t == 0) out0[0] = 0.25f * s * (1.0f / (float)QELEMS);
    }
}

extern "C" void kernel_launch(void* const* d_in, const int* in_sizes, int n_in,
                              void* d_out, int out_size) {
    const float* in  = (const float*)d_in[0];
    const float* emb = (const float*)d_in[1];
    if (n_in >= 2 && in_sizes[0] == EMB_K * DIMS && in_sizes[1] == QELEMS) {
        const float* tmp = in; in = emb; emb = tmp;
    }
    float* out = (float*)d_out;
    float* out_q   = out + 1;
    float* out_idx = out + 1 + QELEMS;

    static bool attr_done = false;
    if (!attr_done) {
        cudaFuncSetAttribute(vq_main, cudaFuncAttributeMaxDynamicSharedMemorySize, SMEM_TOTAL);
        attr_done = true;
    }

    vq_pre<<<32, 32>>>(emb);
    vq_main<<<NCTA, TPB, SMEM_TOTAL>>>(in, emb, out, out_q, out_idx);
}

// round 10
// speedup vs baseline: 2.5870x; 1.2706x over previous
#include <cuda_runtime.h>
#include <cstdint>
#include <cstddef>

#define EMB_K   1024
#define DIMS    64
#define HW_     4096
#define QELEMS  (16*64*64*64)
#define NCTA    512
#define TPB     256
#define MARGIN  3.0f
#define CAP     4
#define RS      80            // smem row stride (bytes) for 64B int8 rows
#define BCHUNK  128           // codes staged per chunk
#define NCHUNK  (EMB_K / BCHUNK)
#define FLUSH_CAP 20

// smem layout (46 KB -> 4 CTAs/SM; regs are the real limiter at 64)
#define OFF_A    0                       // 128 x 80 = 10240
#define OFF_B    10240                   // 128 x 80 = 10240 (reused as cand-idx 128x20)
#define OFF_ENS  20480                   // 1024 float2 = 8192
#define OFF_SX   28672                   // 128 f32
#define OFF_CST  29184                   // 256 thr x 2 x CAP float2 = 16384
#define OFF_CNT  45568                   // 128 int
#define OFF_RB   46080                   // 128 f32
#define OFF_RED  46592                   // 128 f32
#define SMEM_TOTAL 47104

__device__ uint4 g_embq[EMB_K * 4];      // int8 codes, 64B/row
__device__ float g_enorm[EMB_K];
__device__ float g_escale[EMB_K];
__device__ float g_partial[NCTA];
__device__ unsigned int g_ticket;

__device__ __forceinline__ uint32_t smem_u32(const void* p) {
    uint32_t a;
    asm("{ .reg .u64 t; cvta.to.shared.u64 t, %1; cvt.u32.u64 %0, t; }" : "=r"(a) : "l"(p));
    return a;
}

__device__ __forceinline__ void ldsm4(uint32_t* r, uint32_t addr) {
    asm volatile("ldmatrix.sync.aligned.m8n8.x4.shared.b16 {%0,%1,%2,%3}, [%4];"
                 : "=r"(r[0]), "=r"(r[1]), "=r"(r[2]), "=r"(r[3]) : "r"(addr));
}

__device__ __forceinline__ void imma16832(int* c, const uint32_t* a, const uint32_t* b) {
    asm volatile("mma.sync.aligned.m16n8k32.row.col.s32.s8.s8.s32 "
                 "{%0,%1,%2,%3}, {%4,%5,%6,%7}, {%8,%9}, {%0,%1,%2,%3};"
                 : "+r"(c[0]), "+r"(c[1]), "+r"(c[2]), "+r"(c[3])
                 : "r"(a[0]), "r"(a[1]), "r"(a[2]), "r"(a[3]), "r"(b[0]), "r"(b[1]));
}

__device__ __forceinline__ void upd(float& best, int& nc, float2* st, float d, int ci) {
    if (d < best + MARGIN) {
        if (d < best) best = d;
        if (nc == CAP) {
            int m = 0;
#pragma unroll
            for (int q = 0; q < CAP; q++) {
                float2 e = st[q];
                if (e.x < best + MARGIN) st[m++] = e;
            }
            nc = m;
        }
        if (nc < CAP) {
            st[nc] = make_float2(d, __int_as_float(ci));
            nc++;
        } else {
            int wq = 0; float wd = st[0].x;
#pragma unroll
            for (int q = 1; q < CAP; q++) { float v = st[q].x; if (v > wd) { wd = v; wq = q; } }
            if (d < wd) st[wq] = make_float2(d, __int_as_float(ci));
        }
    }
}

__device__ __forceinline__ int q8(float v, float inv) {
    int q = __float2int_rn(v * inv);
    return max(-127, min(127, q));
}

// ---------------- precompute: int8 table + scales + exact fp32 norms ----------------
__global__ void vq_pre(const float* __restrict__ emb) {
    int c = blockIdx.x * blockDim.x + threadIdx.x;
    if (c >= EMB_K) return;
    const float4* er = (const float4*)(emb + (size_t)c * DIMS);
    float4 v[16];
    float s = 0.f, am = 0.f;
#pragma unroll
    for (int i = 0; i < 16; i++) {
        v[i] = __ldg(er + i);
        s += v[i].x * v[i].x + v[i].y * v[i].y + v[i].z * v[i].z + v[i].w * v[i].w;
        am = fmaxf(am, fmaxf(fmaxf(fabsf(v[i].x), fabsf(v[i].y)),
                             fmaxf(fabsf(v[i].z), fabsf(v[i].w))));
    }
    float se  = am * (1.0f / 127.0f);
    float inv = (am > 0.f) ? (127.0f / am) : 0.f;
#pragma unroll
    for (int j = 0; j < 4; j++) {
        uint32_t w[4];
#pragma unroll
        for (int k = 0; k < 4; k++) {
            float4 t = v[j * 4 + k];
            int q0 = q8(t.x, inv), q1 = q8(t.y, inv), q2 = q8(t.z, inv), q3 = q8(t.w, inv);
            w[k] = (uint32_t)(q0 & 0xFF) | ((uint32_t)(q1 & 0xFF) << 8) |
                   ((uint32_t)(q2 & 0xFF) << 16) | ((uint32_t)(q3 & 0xFF) << 24);
        }
        g_embq[c * 4 + j] = make_uint4(w[0], w[1], w[2], w[3]);
    }
    g_enorm[c] = s;
    g_escale[c] = se;
}

// ---------------- fused main kernel ----------------
__global__ void __launch_bounds__(TPB, 4) vq_main(
    const float* __restrict__ in,
    const float* __restrict__ emb,
    float* __restrict__ out0,
    float* __restrict__ out_q,
    float* __restrict__ out_idx)
{
    extern __shared__ char smem[];
    const uint32_t sb = smem_u32(smem);
    const int t = threadIdx.x;
    const int lane = t & 31;
    const int w = t >> 5;
    const int n0blk = blockIdx.x * 128;
    const int b = n0blk >> 12;
    const int hw0 = n0blk & 4095;

    float2* ens = (float2*)(smem + OFF_ENS);
#pragma unroll
    for (int i = 0; i < 4; i++) {
        int c = t + i * TPB;
        ens[c] = make_float2(g_enorm[c], g_escale[c]);
    }
    if (t < 128) ((int*)(smem + OFF_CNT))[t] = 0;

    // ---- A tile: quantize 128 query rows (no persistent x[] regs) ----
    float* sx = (float*)(smem + OFF_SX);
    if (t < 128) {
        const float* xin = in + b * (DIMS * HW_) + hw0 + t;
        float am = 0.f;
#pragma unroll
        for (int k = 0; k < DIMS; k++) am = fmaxf(am, fabsf(__ldg(xin + (size_t)k * HW_)));
        float inv = (am > 0.f) ? (127.0f / am) : 0.f;
        sx[t] = am * (1.0f / 127.0f);
#pragma unroll
        for (int j = 0; j < 4; j++) {
            uint32_t wv[4];
#pragma unroll
            for (int k = 0; k < 4; k++) {
                int i0 = j * 16 + k * 4;
                int q0 = q8(__ldg(xin + (size_t)(i0 + 0) * HW_), inv);
                int q1 = q8(__ldg(xin + (size_t)(i0 + 1) * HW_), inv);
                int q2 = q8(__ldg(xin + (size_t)(i0 + 2) * HW_), inv);
                int q3 = q8(__ldg(xin + (size_t)(i0 + 3) * HW_), inv);
                wv[k] = (uint32_t)(q0 & 0xFF) | ((uint32_t)(q1 & 0xFF) << 8) |
                        ((uint32_t)(q2 & 0xFF) << 16) | ((uint32_t)(q3 & 0xFF) << 24);
            }
            *(uint4*)(smem + OFF_A + t * RS + j * 16) = make_uint4(wv[0], wv[1], wv[2], wv[3]);
        }
    }
    __syncthreads();

    // ---- A fragments: 8 regs cover 16 rows x 64 int8 ----
    const int wr0 = w * 16;
    uint32_t a[8];
    {
        uint32_t base = sb + OFF_A + (uint32_t)((wr0 + (lane & 15)) * RS) + (uint32_t)((lane >> 4) * 16);
        ldsm4(a, base);          // k 0..31
        ldsm4(a + 4, base + 32); // k 32..63
    }

    const int g4 = lane >> 2, tid4 = lane & 3;
    const float msx0 = -2.0f * sx[wr0 + g4];
    const float msx1 = -2.0f * sx[wr0 + 8 + g4];
    float best0 = 3.4e38f, best1 = 3.4e38f;
    int nc0 = 0, nc1 = 0;
    float2* st0 = (float2*)(smem + OFF_CST) + (size_t)t * 2 * CAP;
    float2* st1 = st0 + CAP;

    for (int ch = 0; ch < NCHUNK; ch++) {
        if (ch) __syncthreads();
        // stage B chunk: 128 codes x 64B int8
        const uint4* src = g_embq + ch * (BCHUNK * 4);
#pragma unroll
        for (int i = 0; i < 2; i++) {
            int idx = t + i * TPB;                     // 0..511
            uint4 v = __ldg(src + idx);
            *(uint4*)(smem + OFF_B + (idx >> 2) * RS + (idx & 3) * 16) = v;
        }
        __syncthreads();

        const int cbase = ch * BCHUNK;
#pragma unroll 2
        for (int nt = 0; nt < BCHUNK / 8; nt++) {
            uint32_t bb[4];
            uint32_t baddr = sb + OFF_B + (uint32_t)((nt * 8 + (lane & 7)) * RS)
                             + (uint32_t)((lane >> 3) * 16);
            ldsm4(bb, baddr);
            int accA[4] = {0, 0, 0, 0};
            int accB[4] = {0, 0, 0, 0};
            imma16832(accA, a, bb);          // k 0..31  (independent)
            imma16832(accB, a + 4, bb + 2);  // k 32..63 (independent)

            int c0 = cbase + nt * 8 + 2 * tid4;
            float4 es = *(const float4*)&ens[c0];      // en0, se0, en1, se1
            float d0 = fmaf((float)(accA[0] + accB[0]), msx0 * es.y, es.x);
            float d1 = fmaf((float)(accA[1] + accB[1]), msx0 * es.w, es.z);
            float d2 = fmaf((float)(accA[2] + accB[2]), msx1 * es.y, es.x);
            float d3 = fmaf((float)(accA[3] + accB[3]), msx1 * es.w, es.z);
            upd(best0, nc0, st0, d0, c0);
            upd(best0, nc0, st0, d1, c0 + 1);
            upd(best1, nc1, st1, d2, c0);
            upd(best1, nc1, st1, d3, c0 + 1);
        }
    }

    // ---- row-global coarse minima ----
#pragma unroll
    for (int o = 1; o <= 2; o <<= 1) {
        best0 = fminf(best0, __shfl_xor_sync(0xffffffffu, best0, o));
        best1 = fminf(best1, __shfl_xor_sync(0xffffffffu, best1, o));
    }
    float* rb = (float*)(smem + OFF_RB);
    if (tid4 == 0) { rb[wr0 + g4] = best0; rb[wr0 + 8 + g4] = best1; }
    __syncthreads();

    // ---- flush candidates within margin of the row-global best ----
    int* cnt = (int*)(smem + OFF_CNT);
    int* cix = (int*)(smem + OFF_B);             // reused: 128 rows x FLUSH_CAP idx
    {
        float th0 = rb[wr0 + g4] + MARGIN;
        float th1 = rb[wr0 + 8 + g4] + MARGIN;
        for (int q = 0; q < nc0; q++) {
            float2 e = st0[q];
            if (e.x < th0) {
                int p = atomicAdd(&cnt[wr0 + g4], 1);
                if (p < FLUSH_CAP) cix[(wr0 + g4) * FLUSH_CAP + p] = __float_as_int(e.y);
            }
        }
        for (int q = 0; q < nc1; q++) {
            float2 e = st1[q];
            if (e.x < th1) {
                int p = atomicAdd(&cnt[wr0 + 8 + g4], 1);
                if (p < FLUSH_CAP) cix[(wr0 + 8 + g4) * FLUSH_CAP + p] = __float_as_int(e.y);
            }
        }
    }
    __syncthreads();

    // ---- exact fp32 re-rank + outputs (x re-read from gmem, L1/L2-hot) ----
    float* red = (float*)(smem + OFF_RED);
    if (t < 128) {
        const float* xin = in + b * (DIMS * HW_) + hw0 + t;
        int m = cnt[t]; if (m > FLUSH_CAP) m = FLUSH_CAP;
        float bd = 3.4e38f; int bi = 0x7fffffff;
        for (int q = 0; q < m; q++) {
            int ci = cix[t * FLUSH_CAP + q];
            const float4* er = (const float4*)(emb + (size_t)ci * DIMS);
            float dot = 0.f;
#pragma unroll
            for (int i = 0; i < 16; i++) {
                float4 v = __ldg(er + i);
                dot = fmaf(v.x, __ldg(xin + (size_t)(4 * i + 0) * HW_), dot);
                dot = fmaf(v.y, __ldg(xin + (size_t)(4 * i + 1) * HW_), dot);
                dot = fmaf(v.z, __ldg(xin + (size_t)(4 * i + 2) * HW_), dot);
                dot = fmaf(v.w, __ldg(xin + (size_t)(4 * i + 3) * HW_), dot);
            }
            float ed = fmaf(-2.f, dot, ens[ci].x);
            if (ed < bd || (ed == bd && ci < bi)) { bd = ed; bi = ci; }
        }

        int n = n0blk + t;
        out_idx[n] = (float)bi;
        float* oq = out_q + b * (DIMS * HW_) + hw0 + t;
        const float4* er = (const float4*)(emb + (size_t)bi * DIMS);
        float loss = 0.f;
#pragma unroll
        for (int i = 0; i < 16; i++) {
            float4 v = __ldg(er + i);
            int k = i * 4;
            float x0 = __ldg(xin + (size_t)(k + 0) * HW_);
            float x1 = __ldg(xin + (size_t)(k + 1) * HW_);
            float x2 = __ldg(xin + (size_t)(k + 2) * HW_);
            float x3 = __ldg(xin + (size_t)(k + 3) * HW_);
            float d0 = v.x - x0, d1 = v.y - x1, d2 = v.z - x2, d3 = v.w - x3;
            loss += d0 * d0 + d1 * d1 + d2 * d2 + d3 * d3;
            oq[(size_t)(k + 0) * HW_] = v.x;
            oq[(size_t)(k + 1) * HW_] = v.y;
            oq[(size_t)(k + 2) * HW_] = v.z;
            oq[(size_t)(k + 3) * HW_] = v.w;
        }
        red[t] = loss;
    }
    __syncthreads();
#pragma unroll 1
    for (int s = 64; s > 0; s >>= 1) {
        if (t < s) red[t] += red[t + s];
        __syncthreads();
    }

    // ---- fused finalize: last CTA reduces partials deterministically ----
    __shared__ int slast;
    if (t == 0) {
        g_partial[blockIdx.x] = red[0];
        __threadfence();
        unsigned int old = atomicInc(&g_ticket, NCTA - 1);
        slast = (old == NCTA - 1);
    }
    __syncthreads();
    if (slast && t < 32) {
        __threadfence();
        float s = 0.f;
#pragma unroll
        for (int i = 0; i < NCTA / 32; i++) s += g_partial[t + 32 * i];
#pragma unroll
        for (int o = 16; o > 0; o >>= 1) s += __shfl_down_sync(0xffffffffu, s, o);
        if (t == 0) out0[0] = 0.25f * s * (1.0f / (float)QELEMS);
    }
}

extern "C" void kernel_launch(void* const* d_in, const int* in_sizes, int n_in,
                              void* d_out, int out_size) {
    const float* in  = (const float*)d_in[0];
    const float* emb = (const float*)d_in[1];
    if (n_in >= 2 && in_sizes[0] == EMB_K * DIMS && in_sizes[1] == QELEMS) {
        const float* tmp = in; in = emb; emb = tmp;
    }
    float* out = (float*)d_out;
    float* out_q   = out + 1;
    float* out_idx = out + 1 + QELEMS;

    static bool attr_done = false;
    if (!attr_done) {
        cudaFuncSetAttribute(vq_main, cudaFuncAttributeMaxDynamicSharedMemorySize, SMEM_TOTAL);
        attr_done = true;
    }

    vq_pre<<<32, 32>>>(emb);
    vq_main<<<NCTA, TPB, SMEM_TOTAL>>>(in, emb, out, out_q, out_idx);
}